// round 1
// baseline (speedup 1.0000x reference)
#include <cuda_runtime.h>
#include <math_constants.h>

#define N_BOX 1024
#define P_PTS 4096
#define NTHREADS 256

// float32-rounded constants matching jnp's f32 promotion of python PI
#define PI_F      3.14159274101257324219f   /* (float)np.pi = 3.1415927f */
#define HALF_PI_F 1.57079637050628662109f   /* (float)(np.pi/2) = 1.5707964f */

__device__ float g_mean[N_BOX];
__device__ int   g_valid[N_BOX];

__device__ __forceinline__ float frcp_approx(float x) {
    float r;
    asm("rcp.approx.f32 %0, %1;" : "=f"(r) : "f"(x));
    return r;
}

__global__ __launch_bounds__(NTHREADS, 8)
void wdm3d_box_kernel(const float*  __restrict__ wl,
                      const float*  __restrict__ Ry,
                      const float2* __restrict__ points,
                      const float*  __restrict__ density,
                      const float*  __restrict__ center)
{
    const int n = blockIdx.x;

    // ---------------- per-box constants (redundant per thread; ~300 instrs, negligible)
    const float w  = wl[2 * n];
    const float l  = wl[2 * n + 1];
    const float ry = Ry[n];
    const float ccx = center[2 * n];
    const float ccy = center[2 * n + 1];

    const float init_theta = atanf(w / l);
    const float len = sqrtf(w * w + l * l) * 0.5f;

    const float a0 = init_theta + ry;
    const float a1 = (PI_F - init_theta) + ry;
    const float a2 = (PI_F + init_theta) + ry;
    const float a3 = (-init_theta) + ry;

    const float cx0 = len * cosf(a0) + ccx;
    const float cx1 = len * cosf(a1) + ccx;
    const float cx2 = len * cosf(a2) + ccx;
    const float cx3 = len * cosf(a3) + ccx;
    const float cy0 = len * sinf(a0) + ccy;
    const float cy1 = len * sinf(a1) + ccy;
    const float cy2 = len * sinf(a2) + ccy;
    const float cy3 = len * sinf(a3) + ccy;

    float ry2 = (ry == HALF_PI_F) ? (ry - 0.0001f) : ry;
    ry2 = (ry2 == 0.0f) ? (ry2 + 0.0001f) : ry2;
    const float k1 = tanf(ry2);
    const float k2 = tanf(ry2 + HALF_PI_F);

    const float b11 = cy0 - k1 * cx0;
    const float b12 = cy2 - k1 * cx2;
    const float b21 = cy0 - k2 * cx0;
    const float b22 = cy2 - k2 * cx2;
    // edge order: ks = [k1,k2,k1,k2], bs = [b11,b22,b12,b21]
    const float bs0 = b11, bs1 = b22, bs2 = b12, bs3 = b21;

    const float cxr0 = rintf(cx0 * 10000.0f), cxr1 = rintf(cx1 * 10000.0f);
    const float cxr2 = rintf(cx2 * 10000.0f), cxr3 = rintf(cx3 * 10000.0f);
    const float cyr0 = rintf(cy0 * 10000.0f), cyr1 = rintf(cy1 * 10000.0f);
    const float cyr2 = rintf(cy2 * 10000.0f), cyr3 = rintf(cy3 * 10000.0f);

    // bounds per edge j uses corners j and (j+1)%4
    const float lox0 = fminf(cxr0, cxr1), hix0 = fmaxf(cxr0, cxr1);
    const float lox1 = fminf(cxr1, cxr2), hix1 = fmaxf(cxr1, cxr2);
    const float lox2 = fminf(cxr2, cxr3), hix2 = fmaxf(cxr2, cxr3);
    const float lox3 = fminf(cxr3, cxr0), hix3 = fmaxf(cxr3, cxr0);
    const float loy0 = fminf(cyr0, cyr1), hiy0 = fmaxf(cyr0, cyr1);
    const float loy1 = fminf(cyr1, cyr2), hiy1 = fmaxf(cyr1, cyr2);
    const float loy2 = fminf(cyr2, cyr3), hiy2 = fmaxf(cyr2, cyr3);
    const float loy3 = fminf(cyr3, cyr0), hiy3 = fmaxf(cyr3, cyr0);

    // ---------------- per-point loop
    const float2* __restrict__ pts = points + (size_t)n * P_PTS;
    const float*  __restrict__ den = density + (size_t)n * P_PTS;

    float sum = 0.0f;
    int   cnt = 0;

#pragma unroll 4
    for (int p = threadIdx.x; p < P_PTS; p += NTHREADS) {
        const float2 pt = pts[p];
        const float dens = den[p];

        const float px = (pt.x == 0.0f) ? 0.0001f : pt.x;
        const float py = pt.y;
        const float slope = __fdividef(py, px);

        // only two distinct denominators across the 4 edges
        const float r1 = frcp_approx(slope - k1);
        const float r2 = frcp_approx(slope - k2);

        const float ix0 = bs0 * r1;
        const float ix1 = bs1 * r2;
        const float ix2 = bs2 * r1;
        const float ix3 = bs3 * r2;
        const float iy0 = ix0 * slope;
        const float iy1 = ix1 * slope;
        const float iy2 = ix2 * slope;
        const float iy3 = ix3 * slope;

        const float irx0 = rintf(ix0 * 10000.0f), iry0 = rintf(iy0 * 10000.0f);
        const float irx1 = rintf(ix1 * 10000.0f), iry1 = rintf(iy1 * 10000.0f);
        const float irx2 = rintf(ix2 * 10000.0f), iry2 = rintf(iy2 * 10000.0f);
        const float irx3 = rintf(ix3 * 10000.0f), iry3 = rintf(iy3 * 10000.0f);

        const bool m0 = ((irx0 > lox0) && (irx0 < hix0)) || ((iry0 > loy0) && (iry0 < hiy0));
        const bool m1 = ((irx1 > lox1) && (irx1 < hix1)) || ((iry1 > loy1) && (iry1 < hiy1));
        const bool m2 = ((irx2 > lox2) && (irx2 < hix2)) || ((iry2 > loy2) && (iry2 < hiy2));
        const bool m3 = ((irx3 > lox3) && (irx3 < hix3)) || ((iry3 > loy3) && (iry3 < hiy3));

        const int pc = (int)m0 + (int)m1 + (int)m2 + (int)m3;

        // cen = sqrt(ix^2+iy^2) = |ix| * sqrt(1+slope^2): argmin over masked
        // edges is argmin of |ix| (shared positive factor). Ties -> first index.
        const float dis0 = fabsf(ix0 - px) + fabsf(iy0 - py);
        const float dis1 = fabsf(ix1 - px) + fabsf(iy1 - py);
        const float dis2 = fabsf(ix2 - px) + fabsf(iy2 - py);
        const float dis3 = fabsf(ix3 - px) + fabsf(iy3 - py);

        float best = CUDART_INF_F;
        float dsel = dis0;
        if (m0)                            { best = fabsf(ix0); dsel = dis0; }
        if (m1 && (fabsf(ix1) < best))     { best = fabsf(ix1); dsel = dis1; }
        if (m2 && (fabsf(ix2) < best))     { best = fabsf(ix2); dsel = dis2; }
        if (m3 && (fabsf(ix3) < best))     { best = fabsf(ix3); dsel = dis3; }

        const bool in2 = (pc == 2);
        sum += in2 ? __fdividef(dsel, dens) : 0.0f;
        cnt += in2 ? 1 : 0;
    }

    // ---------------- block reduction (8 warps)
    const unsigned full = 0xFFFFFFFFu;
#pragma unroll
    for (int off = 16; off > 0; off >>= 1) {
        sum += __shfl_down_sync(full, sum, off);
        cnt += __shfl_down_sync(full, cnt, off);
    }

    __shared__ float s_sum[NTHREADS / 32];
    __shared__ int   s_cnt[NTHREADS / 32];
    const int warp = threadIdx.x >> 5;
    const int lane = threadIdx.x & 31;
    if (lane == 0) { s_sum[warp] = sum; s_cnt[warp] = cnt; }
    __syncthreads();

    if (warp == 0) {
        float fs = (lane < NTHREADS / 32) ? s_sum[lane] : 0.0f;
        int   fc = (lane < NTHREADS / 32) ? s_cnt[lane] : 0;
#pragma unroll
        for (int off = 4; off > 0; off >>= 1) {
            fs += __shfl_down_sync(full, fs, off);
            fc += __shfl_down_sync(full, fc, off);
        }
        if (lane == 0) {
            const int   c = fc;
            const float mean = fs / (float)max(c, 1);
            const bool valid = (c >= 3);
            g_mean[n]  = valid ? mean : 0.0f;
            g_valid[n] = valid ? 1 : 0;
        }
    }
}

__global__ __launch_bounds__(1024)
void wdm3d_reduce_kernel(float* __restrict__ out)
{
    const int t = threadIdx.x;
    float s = g_mean[t];
    int   v = g_valid[t];

    const unsigned full = 0xFFFFFFFFu;
#pragma unroll
    for (int off = 16; off > 0; off >>= 1) {
        s += __shfl_down_sync(full, s, off);
        v += __shfl_down_sync(full, v, off);
    }

    __shared__ float s_sum[32];
    __shared__ int   s_cnt[32];
    const int warp = t >> 5;
    const int lane = t & 31;
    if (lane == 0) { s_sum[warp] = s; s_cnt[warp] = v; }
    __syncthreads();

    if (warp == 0) {
        float fs = s_sum[lane];
        int   fv = s_cnt[lane];
#pragma unroll
        for (int off = 16; off > 0; off >>= 1) {
            fs += __shfl_down_sync(full, fs, off);
            fv += __shfl_down_sync(full, fv, off);
        }
        if (lane == 0) {
            out[0] = fs / (float)max(fv, 1);
        }
    }
}

extern "C" void kernel_launch(void* const* d_in, const int* in_sizes, int n_in,
                              void* d_out, int out_size)
{
    const float*  wl      = (const float*)d_in[0];
    const float*  Ry      = (const float*)d_in[1];
    const float2* points  = (const float2*)d_in[2];
    const float*  density = (const float*)d_in[3];
    const float*  center  = (const float*)d_in[4];
    float* out = (float*)d_out;

    wdm3d_box_kernel<<<N_BOX, NTHREADS>>>(wl, Ry, points, density, center);
    wdm3d_reduce_kernel<<<1, 1024>>>(out);
}

// round 2
// speedup vs baseline: 1.3957x; 1.3957x over previous
#include <cuda_runtime.h>
#include <math_constants.h>

#define N_BOX 1024
#define P_PTS 4096
#define NTHREADS 256
#define NWARPS (NTHREADS / 32)

#define PI_F      3.14159274101257324219f
#define HALF_PI_F 1.57079637050628662109f

__device__ float g_mean[N_BOX];
__device__ int   g_valid[N_BOX];
__device__ int   g_count;   // zero-init at load; reset by last block each launch

__device__ __forceinline__ float frcp_approx(float x) {
    float r;
    asm("rcp.approx.f32 %0, %1;" : "=f"(r) : "f"(x));
    return r;
}

struct BoxConsts {
    float k1, k2;
    float bs0, bs1, bs2, bs3;
    float lox0, lox1, lox2, lox3;
    float hix0, hix1, hix2, hix3;
    float loy0, loy1, loy2, loy3;
    float hiy0, hiy1, hiy2, hiy3;
};

__global__ __launch_bounds__(NTHREADS)
void wdm3d_fused_kernel(const float*  __restrict__ wl,
                        const float*  __restrict__ Ry,
                        const float4* __restrict__ points4,
                        const float2* __restrict__ density2,
                        const float*  __restrict__ center,
                        float* __restrict__ out)
{
    const int n = blockIdx.x;
    __shared__ BoxConsts C;

    // ---------------- per-box constants: thread 0 only
    if (threadIdx.x == 0) {
        const float w  = wl[2 * n];
        const float l  = wl[2 * n + 1];
        const float ry = Ry[n];
        const float ccx = center[2 * n];
        const float ccy = center[2 * n + 1];

        const float init_theta = atanf(w / l);
        const float len = sqrtf(w * w + l * l) * 0.5f;

        float s0, c0, s1, c1, s2, c2, s3, c3;
        sincosf(init_theta + ry, &s0, &c0);
        sincosf((PI_F - init_theta) + ry, &s1, &c1);
        sincosf((PI_F + init_theta) + ry, &s2, &c2);
        sincosf((-init_theta) + ry, &s3, &c3);

        const float cx0 = len * c0 + ccx, cy0 = len * s0 + ccy;
        const float cx1 = len * c1 + ccx, cy1 = len * s1 + ccy;
        const float cx2 = len * c2 + ccx, cy2 = len * s2 + ccy;
        const float cx3 = len * c3 + ccx, cy3 = len * s3 + ccy;

        float ry2 = (ry == HALF_PI_F) ? (ry - 0.0001f) : ry;
        ry2 = (ry2 == 0.0f) ? (ry2 + 0.0001f) : ry2;
        const float k1 = tanf(ry2);
        const float k2 = tanf(ry2 + HALF_PI_F);
        C.k1 = k1; C.k2 = k2;

        C.bs0 = cy0 - k1 * cx0;   // b11
        C.bs1 = cy2 - k2 * cx2;   // b22
        C.bs2 = cy2 - k1 * cx2;   // b12
        C.bs3 = cy0 - k2 * cx0;   // b21

        const float cxr0 = rintf(cx0 * 10000.0f), cxr1 = rintf(cx1 * 10000.0f);
        const float cxr2 = rintf(cx2 * 10000.0f), cxr3 = rintf(cx3 * 10000.0f);
        const float cyr0 = rintf(cy0 * 10000.0f), cyr1 = rintf(cy1 * 10000.0f);
        const float cyr2 = rintf(cy2 * 10000.0f), cyr3 = rintf(cy3 * 10000.0f);

        C.lox0 = fminf(cxr0, cxr1); C.hix0 = fmaxf(cxr0, cxr1);
        C.lox1 = fminf(cxr1, cxr2); C.hix1 = fmaxf(cxr1, cxr2);
        C.lox2 = fminf(cxr2, cxr3); C.hix2 = fmaxf(cxr2, cxr3);
        C.lox3 = fminf(cxr3, cxr0); C.hix3 = fmaxf(cxr3, cxr0);
        C.loy0 = fminf(cyr0, cyr1); C.hiy0 = fmaxf(cyr0, cyr1);
        C.loy1 = fminf(cyr1, cyr2); C.hiy1 = fmaxf(cyr1, cyr2);
        C.loy2 = fminf(cyr2, cyr3); C.hiy2 = fmaxf(cyr2, cyr3);
        C.loy3 = fminf(cyr3, cyr0); C.hiy3 = fmaxf(cyr3, cyr0);
    }
    __syncthreads();

    // hoist shared -> registers (loop invariant)
    const float k1 = C.k1, k2 = C.k2;
    const float bs0 = C.bs0, bs1 = C.bs1, bs2 = C.bs2, bs3 = C.bs3;
    const float lox0 = C.lox0, lox1 = C.lox1, lox2 = C.lox2, lox3 = C.lox3;
    const float hix0 = C.hix0, hix1 = C.hix1, hix2 = C.hix2, hix3 = C.hix3;
    const float loy0 = C.loy0, loy1 = C.loy1, loy2 = C.loy2, loy3 = C.loy3;
    const float hiy0 = C.hiy0, hiy1 = C.hiy1, hiy2 = C.hiy2, hiy3 = C.hiy3;

    const float4* __restrict__ pts = points4  + (size_t)n * (P_PTS / 2);
    const float2* __restrict__ den = density2 + (size_t)n * (P_PTS / 2);

    float sum = 0.0f;
    int   cnt = 0;

#define PROCESS_POINT(PX_, PY_, DENS_)                                          \
    do {                                                                        \
        const float px = ((PX_) == 0.0f) ? 0.0001f : (PX_);                     \
        const float py = (PY_);                                                 \
        const float slope = py * frcp_approx(px);                               \
        const float r1 = frcp_approx(slope - k1);                               \
        const float r2 = frcp_approx(slope - k2);                               \
        const float ix0 = bs0 * r1, ix1 = bs1 * r2;                             \
        const float ix2 = bs2 * r1, ix3 = bs3 * r2;                             \
        const float iy0 = ix0 * slope, iy1 = ix1 * slope;                       \
        const float iy2 = ix2 * slope, iy3 = ix3 * slope;                       \
        const float irx0 = rintf(ix0 * 10000.0f), iry0 = rintf(iy0 * 10000.0f); \
        const float irx1 = rintf(ix1 * 10000.0f), iry1 = rintf(iy1 * 10000.0f); \
        const float irx2 = rintf(ix2 * 10000.0f), iry2 = rintf(iy2 * 10000.0f); \
        const float irx3 = rintf(ix3 * 10000.0f), iry3 = rintf(iy3 * 10000.0f); \
        const bool m0 = ((irx0 > lox0) && (irx0 < hix0)) ||                     \
                        ((iry0 > loy0) && (iry0 < hiy0));                       \
        const bool m1 = ((irx1 > lox1) && (irx1 < hix1)) ||                     \
                        ((iry1 > loy1) && (iry1 < hiy1));                       \
        const bool m2 = ((irx2 > lox2) && (irx2 < hix2)) ||                     \
                        ((iry2 > loy2) && (iry2 < hiy2));                       \
        const bool m3 = ((irx3 > lox3) && (irx3 < hix3)) ||                     \
                        ((iry3 > loy3) && (iry3 < hiy3));                       \
        const int pc = (int)m0 + (int)m1 + (int)m2 + (int)m3;                   \
        /* argmin of cen == argmin of |ix| (shared positive factor) */          \
        float best = CUDART_INF_F;                                              \
        float bix = ix0, biy = iy0;                                             \
        if (m0)                        { best = fabsf(ix0); bix = ix0; biy = iy0; } \
        if (m1 && (fabsf(ix1) < best)) { best = fabsf(ix1); bix = ix1; biy = iy1; } \
        if (m2 && (fabsf(ix2) < best)) { best = fabsf(ix2); bix = ix2; biy = iy2; } \
        if (m3 && (fabsf(ix3) < best)) { best = fabsf(ix3); bix = ix3; biy = iy3; } \
        if (pc == 2) {                                                          \
            const float dsel = fabsf(bix - px) + fabsf(biy - py);               \
            sum += dsel * frcp_approx(DENS_);                                   \
            cnt += 1;                                                           \
        }                                                                       \
    } while (0)

#pragma unroll 2
    for (int i = threadIdx.x; i < P_PTS / 2; i += NTHREADS) {
        const float4 p  = pts[i];
        const float2 d2 = den[i];
        PROCESS_POINT(p.x, p.y, d2.x);
        PROCESS_POINT(p.z, p.w, d2.y);
    }

    // ---------------- block reduction
    const unsigned full = 0xFFFFFFFFu;
#pragma unroll
    for (int off = 16; off > 0; off >>= 1) {
        sum += __shfl_down_sync(full, sum, off);
        cnt += __shfl_down_sync(full, cnt, off);
    }

    __shared__ float s_sum[NWARPS];
    __shared__ int   s_cnt[NWARPS];
    __shared__ bool  s_last;
    const int warp = threadIdx.x >> 5;
    const int lane = threadIdx.x & 31;
    if (lane == 0) { s_sum[warp] = sum; s_cnt[warp] = cnt; }
    __syncthreads();

    if (threadIdx.x == 0) {
        float fs = 0.0f; int fc = 0;
#pragma unroll
        for (int wi = 0; wi < NWARPS; wi++) { fs += s_sum[wi]; fc += s_cnt[wi]; }
        const bool valid = (fc >= 3);
        g_mean[n]  = valid ? (fs / (float)max(fc, 1)) : 0.0f;
        g_valid[n] = valid ? 1 : 0;
        __threadfence();
        const int prev = atomicAdd(&g_count, 1);
        s_last = (prev == gridDim.x - 1);
    }
    __syncthreads();

    // ---------------- last block: final deterministic reduction
    if (s_last) {
        float fs = 0.0f;
        int   fv = 0;
#pragma unroll
        for (int j = 0; j < N_BOX / NTHREADS; j++) {
            const int idx = threadIdx.x + j * NTHREADS;
            fs += __ldcg(&g_mean[idx]);
            fv += __ldcg(&g_valid[idx]);
        }
#pragma unroll
        for (int off = 16; off > 0; off >>= 1) {
            fs += __shfl_down_sync(full, fs, off);
            fv += __shfl_down_sync(full, fv, off);
        }
        __shared__ float f_sum[NWARPS];
        __shared__ int   f_cnt[NWARPS];
        if (lane == 0) { f_sum[warp] = fs; f_cnt[warp] = fv; }
        __syncthreads();
        if (threadIdx.x == 0) {
            float ts = 0.0f; int tv = 0;
#pragma unroll
            for (int wi = 0; wi < NWARPS; wi++) { ts += f_sum[wi]; tv += f_cnt[wi]; }
            out[0] = ts / (float)max(tv, 1);
            g_count = 0;   // reset for next graph replay
        }
    }
}

extern "C" void kernel_launch(void* const* d_in, const int* in_sizes, int n_in,
                              void* d_out, int out_size)
{
    const float*  wl      = (const float*)d_in[0];
    const float*  Ry      = (const float*)d_in[1];
    const float4* points4 = (const float4*)d_in[2];
    const float2* density2= (const float2*)d_in[3];
    const float*  center  = (const float*)d_in[4];
    float* out = (float*)d_out;

    wdm3d_fused_kernel<<<N_BOX, NTHREADS>>>(wl, Ry, points4, density2, center, out);
}

// round 3
// speedup vs baseline: 1.4171x; 1.0153x over previous
#include <cuda_runtime.h>
#include <math_constants.h>

#define N_BOX 1024
#define P_PTS 4096
#define NTHREADS 256
#define NWARPS (NTHREADS / 32)
#define SPLIT 2
#define NBLOCKS (N_BOX * SPLIT)
#define PTS_PER_BLK (P_PTS / SPLIT)          /* 2048 */
#define VEC_PER_BLK (PTS_PER_BLK / 2)        /* 1024 float4 */

#define PI_F      3.14159274101257324219f
#define HALF_PI_F 1.57079637050628662109f

__device__ float g_psum[NBLOCKS];
__device__ int   g_pcnt[NBLOCKS];
__device__ int   g_count;   // zero-init at load; reset by last block each launch

__device__ __forceinline__ float frcp_approx(float x) {
    float r;
    asm("rcp.approx.f32 %0, %1;" : "=f"(r) : "f"(x));
    return r;
}

struct BoxConsts {
    float k1, k2;
    float bs0, bs1, bs2, bs3;
    // pre-scaled open-interval thresholds: compare ix/iy directly
    float LOX0, LOX1, LOX2, LOX3;
    float HIX0, HIX1, HIX2, HIX3;
    float LOY0, LOY1, LOY2, LOY3;
    float HIY0, HIY1, HIY2, HIY3;
};

__global__ __launch_bounds__(NTHREADS)
void wdm3d_fused_kernel(const float*  __restrict__ wl,
                        const float*  __restrict__ Ry,
                        const float4* __restrict__ points4,
                        const float2* __restrict__ density2,
                        const float*  __restrict__ center,
                        float* __restrict__ out)
{
    const int blk  = blockIdx.x;
    const int n    = blk >> 1;        // box index
    const int half = blk & 1;         // which half of the point set
    __shared__ BoxConsts C;

    // ---------------- per-box constants: thread 0 only
    if (threadIdx.x == 0) {
        const float w  = wl[2 * n];
        const float l  = wl[2 * n + 1];
        const float ry = Ry[n];
        const float ccx = center[2 * n];
        const float ccy = center[2 * n + 1];

        const float init_theta = atanf(w / l);
        const float len = sqrtf(w * w + l * l) * 0.5f;

        float s0, c0, s1, c1, s2, c2, s3, c3;
        sincosf(init_theta + ry, &s0, &c0);
        sincosf((PI_F - init_theta) + ry, &s1, &c1);
        sincosf((PI_F + init_theta) + ry, &s2, &c2);
        sincosf((-init_theta) + ry, &s3, &c3);

        const float cx0 = len * c0 + ccx, cy0 = len * s0 + ccy;
        const float cx1 = len * c1 + ccx, cy1 = len * s1 + ccy;
        const float cx2 = len * c2 + ccx, cy2 = len * s2 + ccy;
        const float cx3 = len * c3 + ccx, cy3 = len * s3 + ccy;

        float ry2 = (ry == HALF_PI_F) ? (ry - 0.0001f) : ry;
        ry2 = (ry2 == 0.0f) ? (ry2 + 0.0001f) : ry2;
        const float k1 = tanf(ry2);
        const float k2 = tanf(ry2 + HALF_PI_F);
        C.k1 = k1; C.k2 = k2;

        C.bs0 = cy0 - k1 * cx0;   // b11
        C.bs1 = cy2 - k2 * cx2;   // b22
        C.bs2 = cy2 - k1 * cx2;   // b12
        C.bs3 = cy0 - k2 * cx0;   // b21

        const float cxr0 = rintf(cx0 * 10000.0f), cxr1 = rintf(cx1 * 10000.0f);
        const float cxr2 = rintf(cx2 * 10000.0f), cxr3 = rintf(cx3 * 10000.0f);
        const float cyr0 = rintf(cy0 * 10000.0f), cyr1 = rintf(cy1 * 10000.0f);
        const float cyr2 = rintf(cy2 * 10000.0f), cyr3 = rintf(cy3 * 10000.0f);

        // rint(v*1e4) > lo  <=>  v > (lo+0.5)*1e-4   (ties measure-zero)
        const float S = 1e-4f;
        C.LOX0 = (fminf(cxr0, cxr1) + 0.5f) * S; C.HIX0 = (fmaxf(cxr0, cxr1) - 0.5f) * S;
        C.LOX1 = (fminf(cxr1, cxr2) + 0.5f) * S; C.HIX1 = (fmaxf(cxr1, cxr2) - 0.5f) * S;
        C.LOX2 = (fminf(cxr2, cxr3) + 0.5f) * S; C.HIX2 = (fmaxf(cxr2, cxr3) - 0.5f) * S;
        C.LOX3 = (fminf(cxr3, cxr0) + 0.5f) * S; C.HIX3 = (fmaxf(cxr3, cxr0) - 0.5f) * S;
        C.LOY0 = (fminf(cyr0, cyr1) + 0.5f) * S; C.HIY0 = (fmaxf(cyr0, cyr1) - 0.5f) * S;
        C.LOY1 = (fminf(cyr1, cyr2) + 0.5f) * S; C.HIY1 = (fmaxf(cyr1, cyr2) - 0.5f) * S;
        C.LOY2 = (fminf(cyr2, cyr3) + 0.5f) * S; C.HIY2 = (fmaxf(cyr2, cyr3) - 0.5f) * S;
        C.LOY3 = (fminf(cyr3, cyr0) + 0.5f) * S; C.HIY3 = (fmaxf(cyr3, cyr0) - 0.5f) * S;
    }
    __syncthreads();

    // hoist to registers
    const float k1 = C.k1, k2 = C.k2;
    const float bs0 = C.bs0, bs1 = C.bs1, bs2 = C.bs2, bs3 = C.bs3;
    const float LOX0 = C.LOX0, LOX1 = C.LOX1, LOX2 = C.LOX2, LOX3 = C.LOX3;
    const float HIX0 = C.HIX0, HIX1 = C.HIX1, HIX2 = C.HIX2, HIX3 = C.HIX3;
    const float LOY0 = C.LOY0, LOY1 = C.LOY1, LOY2 = C.LOY2, LOY3 = C.LOY3;
    const float HIY0 = C.HIY0, HIY1 = C.HIY1, HIY2 = C.HIY2, HIY3 = C.HIY3;

    const size_t base = (size_t)n * (P_PTS / 2) + (size_t)half * VEC_PER_BLK;
    const float4* __restrict__ pts = points4  + base;
    const float2* __restrict__ den = density2 + base;

    float sum = 0.0f;
    int   cnt = 0;

#define PROCESS_POINT(PX_, PY_, DENS_)                                          \
    do {                                                                        \
        const float px = ((PX_) == 0.0f) ? 0.0001f : (PX_);                     \
        const float py = (PY_);                                                 \
        /* ix = bs*px/(py - k*px), iy = bs*py/(py - k*px)  (slope eliminated) */\
        const float t1 = frcp_approx(fmaf(-k1, px, py));                        \
        const float t2 = frcp_approx(fmaf(-k2, px, py));                        \
        const float u1 = px * t1, v1 = py * t1;                                 \
        const float u2 = px * t2, v2 = py * t2;                                 \
        const float ix0 = bs0 * u1, iy0 = bs0 * v1;                             \
        const float ix1 = bs1 * u2, iy1 = bs1 * v2;                             \
        const float ix2 = bs2 * u1, iy2 = bs2 * v1;                             \
        const float ix3 = bs3 * u2, iy3 = bs3 * v2;                             \
        const bool m0 = ((ix0 > LOX0) && (ix0 < HIX0)) ||                       \
                        ((iy0 > LOY0) && (iy0 < HIY0));                         \
        const bool m1 = ((ix1 > LOX1) && (ix1 < HIX1)) ||                       \
                        ((iy1 > LOY1) && (iy1 < HIY1));                         \
        const bool m2 = ((ix2 > LOX2) && (ix2 < HIX2)) ||                       \
                        ((iy2 > LOY2) && (iy2 < HIY2));                         \
        const bool m3 = ((ix3 > LOX3) && (ix3 < HIX3)) ||                       \
                        ((iy3 > LOY3) && (iy3 < HIY3));                         \
        const int pc = (int)m0 + (int)m1 + (int)m2 + (int)m3;                   \
        /* argmin cen == argmin |ix| (shared positive factor sqrt(1+slope^2)) */\
        float best = CUDART_INF_F;                                              \
        float bix = ix0, biy = iy0;                                             \
        if (m0)                        { best = fabsf(ix0); bix = ix0; biy = iy0; } \
        if (m1 && (fabsf(ix1) < best)) { best = fabsf(ix1); bix = ix1; biy = iy1; } \
        if (m2 && (fabsf(ix2) < best)) { best = fabsf(ix2); bix = ix2; biy = iy2; } \
        if (m3 && (fabsf(ix3) < best)) { best = fabsf(ix3); bix = ix3; biy = iy3; } \
        if (pc == 2) {                                                          \
            const float dsel = fabsf(bix - px) + fabsf(biy - py);               \
            sum += dsel * frcp_approx(DENS_);                                   \
            cnt += 1;                                                           \
        }                                                                       \
    } while (0)

#pragma unroll 2
    for (int i = threadIdx.x; i < VEC_PER_BLK; i += NTHREADS) {
        const float4 p  = pts[i];
        const float2 d2 = den[i];
        PROCESS_POINT(p.x, p.y, d2.x);
        PROCESS_POINT(p.z, p.w, d2.y);
    }

    // ---------------- block reduction
    const unsigned full = 0xFFFFFFFFu;
#pragma unroll
    for (int off = 16; off > 0; off >>= 1) {
        sum += __shfl_down_sync(full, sum, off);
        cnt += __shfl_down_sync(full, cnt, off);
    }

    __shared__ float s_sum[NWARPS];
    __shared__ int   s_cnt[NWARPS];
    __shared__ bool  s_last;
    const int warp = threadIdx.x >> 5;
    const int lane = threadIdx.x & 31;
    if (lane == 0) { s_sum[warp] = sum; s_cnt[warp] = cnt; }
    __syncthreads();

    if (threadIdx.x == 0) {
        float fs = 0.0f; int fc = 0;
#pragma unroll
        for (int wi = 0; wi < NWARPS; wi++) { fs += s_sum[wi]; fc += s_cnt[wi]; }
        g_psum[blk] = fs;
        g_pcnt[blk] = fc;
        __threadfence();
        const int prev = atomicAdd(&g_count, 1);
        s_last = (prev == gridDim.x - 1);
    }
    __syncthreads();

    // ---------------- last block: deterministic final reduction over boxes
    if (s_last) {
        float fs = 0.0f;
        int   fv = 0;
#pragma unroll
        for (int j = 0; j < N_BOX / NTHREADS; j++) {
            const int b = threadIdx.x + j * NTHREADS;      // box index
            const float bsum = __ldcg(&g_psum[2 * b]) + __ldcg(&g_psum[2 * b + 1]);
            const int   bcnt = __ldcg(&g_pcnt[2 * b]) + __ldcg(&g_pcnt[2 * b + 1]);
            const bool valid = (bcnt >= 3);
            fs += valid ? (bsum / (float)max(bcnt, 1)) : 0.0f;
            fv += valid ? 1 : 0;
        }
#pragma unroll
        for (int off = 16; off > 0; off >>= 1) {
            fs += __shfl_down_sync(full, fs, off);
            fv += __shfl_down_sync(full, fv, off);
        }
        __shared__ float f_sum[NWARPS];
        __shared__ int   f_cnt[NWARPS];
        if (lane == 0) { f_sum[warp] = fs; f_cnt[warp] = fv; }
        __syncthreads();
        if (threadIdx.x == 0) {
            float ts = 0.0f; int tv = 0;
#pragma unroll
            for (int wi = 0; wi < NWARPS; wi++) { ts += f_sum[wi]; tv += f_cnt[wi]; }
            out[0] = ts / (float)max(tv, 1);
            g_count = 0;   // reset for next graph replay
        }
    }
}

extern "C" void kernel_launch(void* const* d_in, const int* in_sizes, int n_in,
                              void* d_out, int out_size)
{
    const float*  wl       = (const float*)d_in[0];
    const float*  Ry       = (const float*)d_in[1];
    const float4* points4  = (const float4*)d_in[2];
    const float2* density2 = (const float2*)d_in[3];
    const float*  center   = (const float*)d_in[4];
    float* out = (float*)d_out;

    wdm3d_fused_kernel<<<NBLOCKS, NTHREADS>>>(wl, Ry, points4, density2, center, out);
}